// round 1
// baseline (speedup 1.0000x reference)
#include <cuda_runtime.h>

// EGNN layer, fused per-node kernel.
// B=2, N=16384, K=16, H=128.
// Block = 4 nodes (NPB), 128 threads = 1 output channel each.
// All edge-MLP intermediates live in shared memory, transposed to [row][k]
// so the K=16 accumulation vectorizes as float4/f32x2 loads.
// FP32 math via Blackwell packed fma.rn.f32x2 (2 FMA per instruction).

#define HH   128
#define NB_  2
#define NN   16384
#define KK   16
#define NPB  4
#define PADK 20
#define NTH  128

typedef unsigned long long ull;

__device__ __forceinline__ ull pk2(float w) {
    ull r; asm("mov.b64 %0, {%1, %1};" : "=l"(r) : "f"(w)); return r;
}
__device__ __forceinline__ void fma2(ull &d, ull a, ull b) {
    asm("fma.rn.f32x2 %0, %1, %2, %0;" : "+l"(d) : "l"(a), "l"(b));
}
__device__ __forceinline__ float2 up2(ull v) {
    float2 f; asm("mov.b64 {%0, %1}, %2;" : "=f"(f.x), "=f"(f.y) : "l"(v)); return f;
}
__device__ __forceinline__ float silu_f(float v) { return v / (1.0f + __expf(-v)); }

// Shared-memory float offsets
#define OFF_HJT 0            // NPB*128*PADK = 10240 floats (also holds m_ijT in phase 3)
#define OFF_M1T 10240        // 10240 floats (also prS, stride 129, in coord reduce)
#define OFF_HIS 20480        // 512 floats, layout [i][nb]
#define OFF_MIS 20992        // 512 floats, layout [i][nb]
#define OFF_N1S 21504        // 512 floats, layout [i][nb]
#define OFF_SQD 22016        // 64
#define OFF_XD  22080        // 192  [nb][k][d]
#define OFF_XI  22272        // 16 (12 used)
#define OFF_CW  22288        // 64
#define OFF_IDX 22352        // 64 ints
#define SMEM_FLOATS 22416
#define SMEM_BYTES (SMEM_FLOATS * 4)

// inT: [NPB][128][PADK] smem, Wc: weight column base (W + o), stride HH rows.
// acc[nb][kp] accumulates packed pairs (k=2kp, 2kp+1).
__device__ __forceinline__ void gemm16(const float* __restrict__ inT,
                                       const float* __restrict__ Wc,
                                       ull (&acc)[NPB][8]) {
    float wbuf[8];
#pragma unroll
    for (int q = 0; q < 8; ++q) wbuf[q] = Wc[q * HH];
#pragma unroll 1
    for (int ib = 0; ib < HH; ib += 8) {
        float wnext[8];
#pragma unroll
        for (int q = 0; q < 8; ++q) wnext[q] = 0.0f;
        if (ib + 8 < HH) {
#pragma unroll
            for (int q = 0; q < 8; ++q) wnext[q] = Wc[(ib + 8 + q) * HH];
        }
#pragma unroll
        for (int q = 0; q < 8; ++q) {
            int i = ib + q;
            ull wp = pk2(wbuf[q]);
#pragma unroll
            for (int nb = 0; nb < NPB; ++nb) {
                const float* bp = inT + (nb * HH + i) * PADK;
                ulonglong2 v0 = *(const ulonglong2*)(bp);
                ulonglong2 v1 = *(const ulonglong2*)(bp + 4);
                ulonglong2 v2 = *(const ulonglong2*)(bp + 8);
                ulonglong2 v3 = *(const ulonglong2*)(bp + 12);
                fma2(acc[nb][0], v0.x, wp);
                fma2(acc[nb][1], v0.y, wp);
                fma2(acc[nb][2], v1.x, wp);
                fma2(acc[nb][3], v1.y, wp);
                fma2(acc[nb][4], v2.x, wp);
                fma2(acc[nb][5], v2.y, wp);
                fma2(acc[nb][6], v3.x, wp);
                fma2(acc[nb][7], v3.y, wp);
            }
        }
#pragma unroll
        for (int q = 0; q < 8; ++q) wbuf[q] = wnext[q];
    }
}

__global__ void __launch_bounds__(NTH, 2)
egnn_kernel(const float* __restrict__ h, const float* __restrict__ x,
            const int* __restrict__ eidx,
            const float* __restrict__ We1, const float* __restrict__ be1,
            const float* __restrict__ We2, const float* __restrict__ be2,
            const float* __restrict__ Wc1, const float* __restrict__ bc1,
            const float* __restrict__ Wc2,
            const float* __restrict__ Wn1, const float* __restrict__ bn1,
            const float* __restrict__ Wn2, const float* __restrict__ bn2,
            float* __restrict__ out) {
    extern __shared__ float sm[];
    float* hjT  = sm + OFF_HJT;
    float* m1T  = sm + OFF_M1T;
    float* prS  = sm + OFF_M1T;   // reuse: [64][129]
    float* hiS  = sm + OFF_HIS;
    float* miS  = sm + OFF_MIS;
    float* n1S  = sm + OFF_N1S;
    float* sqdS = sm + OFF_SQD;
    float* xdS  = sm + OFF_XD;
    float* xiS  = sm + OFF_XI;
    float* cwS  = sm + OFF_CW;
    int*   idxS = (int*)(sm + OFF_IDX);

    const int t  = threadIdx.x;
    const int g  = blockIdx.x;
    const int b  = g >> 12;                 // 4096 groups per batch
    const int n0 = (g & 4095) * NPB;
    const long base_bn = (long)b * NN;

    // ---- stage inputs ----
    if (t < NPB * KK) idxS[t] = eidx[(base_bn + n0 + (t >> 4)) * KK + (t & 15)];
    if (t < NPB * 3)  xiS[t]  = x[(base_bn + n0 + t / 3) * 3 + (t % 3)];
    {
        float4 hv;
        hv.x = h[(base_bn + n0 + 0) * HH + t];
        hv.y = h[(base_bn + n0 + 1) * HH + t];
        hv.z = h[(base_bn + n0 + 2) * HH + t];
        hv.w = h[(base_bn + n0 + 3) * HH + t];
        *(float4*)(hiS + t * 4) = hv;
    }
    __syncthreads();

    // x_diff / sq_dist per edge
    if (t < NPB * KK) {
        int j  = idxS[t];
        int nb = t >> 4;
        const float* xj = x + (base_bn + j) * 3;
        float dx = xiS[nb * 3 + 0] - xj[0];
        float dy = xiS[nb * 3 + 1] - xj[1];
        float dz = xiS[nb * 3 + 2] - xj[2];
        xdS[t * 3 + 0] = dx; xdS[t * 3 + 1] = dy; xdS[t * 3 + 2] = dz;
        sqdS[t] = dx * dx + dy * dy + dz * dz;
    }
    // gather h_neigh, transposed into hjT[nb][channel][k]
    {
        int w32 = t >> 5, c = t & 31;
        for (int e = w32; e < NPB * KK; e += 4) {
            int j  = idxS[e];
            int nb = e >> 4, k = e & 15;
            const float* hj = h + (base_bn + j) * HH;
#pragma unroll
            for (int r = 0; r < 4; ++r) {
                hjT[(nb * HH + c + 32 * r) * PADK + k] = hj[c + 32 * r];
            }
        }
    }
    __syncthreads();

    const int o = t;

    // ---- s_i = h_i @ We1[0:128, o]  (k-invariant part of layer 1) ----
    ull s01 = 0ull, s23 = 0ull;
    {
        const float* Wc = We1 + o;
#pragma unroll 8
        for (int i = 0; i < HH; ++i) {
            ull wp = pk2(Wc[i * HH]);
            ulonglong2 hv = *(const ulonglong2*)(hiS + i * 4);
            fma2(s01, hv.x, wp);
            fma2(s23, hv.y, wp);
        }
    }

    ull acc[NPB][8];

    // ---- layer 1: m1 = silu(feat @ We1 + be1) ----
#pragma unroll
    for (int nb = 0; nb < NPB; ++nb)
#pragma unroll
        for (int q = 0; q < 8; ++q) acc[nb][q] = 0ull;
    gemm16(hjT, We1 + 128 * HH + o, acc);
    {
        float b1v = be1[o];
        float wsq = We1[256 * HH + o];
        float2 si01 = up2(s01), si23 = up2(s23);
        float sif[4] = {si01.x, si01.y, si23.x, si23.y};
#pragma unroll
        for (int nb = 0; nb < NPB; ++nb) {
            float outk[16];
#pragma unroll
            for (int kp = 0; kp < 8; ++kp) {
                float2 v = up2(acc[nb][kp]);
                int k0 = kp * 2;
                outk[k0]     = silu_f(v.x + sif[nb] + b1v + sqdS[nb * 16 + k0] * wsq);
                outk[k0 + 1] = silu_f(v.y + sif[nb] + b1v + sqdS[nb * 16 + k0 + 1] * wsq);
            }
            float* dst = m1T + (nb * HH + o) * PADK;
#pragma unroll
            for (int q = 0; q < 4; ++q)
                *(float4*)(dst + q * 4) =
                    make_float4(outk[q*4], outk[q*4+1], outk[q*4+2], outk[q*4+3]);
        }
    }
    __syncthreads();

    // ---- layer 2: m_ij = silu(m1 @ We2 + be2); m_i = sum_k m_ij ----
#pragma unroll
    for (int nb = 0; nb < NPB; ++nb)
#pragma unroll
        for (int q = 0; q < 8; ++q) acc[nb][q] = 0ull;
    gemm16(m1T, We2 + o, acc);
    {
        float b2v = be2[o];
        float mi[4];
#pragma unroll
        for (int nb = 0; nb < NPB; ++nb) {
            float outk[16];
            float s = 0.0f;
#pragma unroll
            for (int kp = 0; kp < 8; ++kp) {
                float2 v = up2(acc[nb][kp]);
                int k0 = kp * 2;
                float m0 = silu_f(v.x + b2v);
                float m1v = silu_f(v.y + b2v);
                outk[k0] = m0; outk[k0 + 1] = m1v;
                s += m0 + m1v;
            }
            mi[nb] = s;
            float* dst = hjT + (nb * HH + o) * PADK;   // reuse hjT for m_ijT
#pragma unroll
            for (int q = 0; q < 4; ++q)
                *(float4*)(dst + q * 4) =
                    make_float4(outk[q*4], outk[q*4+1], outk[q*4+2], outk[q*4+3]);
        }
        *(float4*)(miS + o * 4) = make_float4(mi[0], mi[1], mi[2], mi[3]);
    }
    __syncthreads();

    // ---- layer 3: c1 = silu(m_ij @ Wc1 + bc1); partials of c1 @ Wc2 ----
#pragma unroll
    for (int nb = 0; nb < NPB; ++nb)
#pragma unroll
        for (int q = 0; q < 8; ++q) acc[nb][q] = 0ull;
    gemm16(hjT, Wc1 + o, acc);
    {
        float b3v  = bc1[o];
        float wc2v = Wc2[o];
#pragma unroll
        for (int nb = 0; nb < NPB; ++nb) {
#pragma unroll
            for (int kp = 0; kp < 8; ++kp) {
                float2 v = up2(acc[nb][kp]);
                int k0 = nb * 16 + kp * 2;
                prS[k0 * 129 + o]       = silu_f(v.x + b3v) * wc2v;
                prS[(k0 + 1) * 129 + o] = silu_f(v.y + b3v) * wc2v;
            }
        }
    }
    __syncthreads();

    // reduce coord_w over the 128 channels (conflict-free, stride 129)
    if (t < NPB * KK) {
        const float* row = prS + t * 129;
        float s = 0.0f;
#pragma unroll 8
        for (int i = 0; i < HH; ++i) s += row[i];
        cwS[t] = s;
    }
    __syncthreads();

    // x_new
    if (t < NPB * 3) {
        int nb = t / 3, d = t % 3;
        float s = 0.0f;
#pragma unroll
        for (int k = 0; k < KK; ++k)
            s += xdS[(nb * 16 + k) * 3 + d] * cwS[nb * 16 + k];
        out[(long)NB_ * NN * HH + (base_bn + n0 + nb) * 3 + d] =
            xiS[t] + s * (1.0f / 16.0f);
    }

    // ---- node MLP ----
    ull a01 = 0ull, a23 = 0ull;
    {
        const float* W1h = Wn1 + o;
        const float* W1m = Wn1 + 128 * HH + o;
#pragma unroll 4
        for (int i = 0; i < HH; ++i) {
            ull w1p = pk2(W1h[i * HH]);
            ull w2p = pk2(W1m[i * HH]);
            ulonglong2 hv = *(const ulonglong2*)(hiS + i * 4);
            ulonglong2 mv = *(const ulonglong2*)(miS + i * 4);
            fma2(a01, hv.x, w1p); fma2(a23, hv.y, w1p);
            fma2(a01, mv.x, w2p); fma2(a23, mv.y, w2p);
        }
    }
    {
        float bn1v = bn1[o];
        float2 u01 = up2(a01), u23 = up2(a23);
        *(float4*)(n1S + o * 4) = make_float4(silu_f(u01.x + bn1v), silu_f(u01.y + bn1v),
                                              silu_f(u23.x + bn1v), silu_f(u23.y + bn1v));
    }
    __syncthreads();
    a01 = 0ull; a23 = 0ull;
    {
        const float* W2c = Wn2 + o;
#pragma unroll 4
        for (int i = 0; i < HH; ++i) {
            ull wp = pk2(W2c[i * HH]);
            ulonglong2 nv = *(const ulonglong2*)(n1S + i * 4);
            fma2(a01, nv.x, wp); fma2(a23, nv.y, wp);
        }
    }
    {
        float bn2v = bn2[o];
        float2 u01 = up2(a01), u23 = up2(a23);
        float hn[4] = {u01.x, u01.y, u23.x, u23.y};
#pragma unroll
        for (int nb = 0; nb < NPB; ++nb)
            out[(base_bn + n0 + nb) * HH + o] = hn[nb] + bn2v + hiS[o * 4 + nb];
    }
}

extern "C" void kernel_launch(void* const* d_in, const int* in_sizes, int n_in,
                              void* d_out, int out_size) {
    const float* h   = (const float*)d_in[0];
    const float* x   = (const float*)d_in[1];
    const int*   ei  = (const int*)d_in[2];
    const float* We1 = (const float*)d_in[3];
    const float* be1 = (const float*)d_in[4];
    const float* We2 = (const float*)d_in[5];
    const float* be2 = (const float*)d_in[6];
    const float* Wc1 = (const float*)d_in[7];
    const float* bc1 = (const float*)d_in[8];
    const float* Wc2 = (const float*)d_in[9];
    const float* Wn1 = (const float*)d_in[10];
    const float* bn1 = (const float*)d_in[11];
    const float* Wn2 = (const float*)d_in[12];
    const float* bn2 = (const float*)d_in[13];
    float* out = (float*)d_out;

    cudaFuncSetAttribute(egnn_kernel, cudaFuncAttributeMaxDynamicSharedMemorySize,
                         SMEM_BYTES);
    dim3 grid(NB_ * NN / NPB);   // 8192 blocks
    egnn_kernel<<<grid, NTH, SMEM_BYTES>>>(h, x, ei, We1, be1, We2, be2,
                                           Wc1, bc1, Wc2, Wn1, bn1, Wn2, bn2, out);
}